// round 5
// baseline (speedup 1.0000x reference)
#include <cuda_runtime.h>
#include <cstdint>

#define BS   4
#define NVW  12
#define CIN  384
#define COUT 32
#define HH   64
#define WW   64
#define HW   4096
#define NIMG (BS * NVW)
#define NVOX (64 * 64 * 64)

// Scratch: reduced features in (img, pixel, channel) layout -> 25.2 MB, L2-resident.
__device__ float g_red[(size_t)NIMG * HW * COUT];

// ---------------------------------------------------------------------------
// Kernel A: channel reduce 384 -> 32 with packed f32x2 FMAs.
// Each thread: 2 adjacent pixels (packed in f32x2), all 32 output channels.
// Weights staged in dynamic smem as duplicated {w,w} 64-bit pairs (96 KB),
// read via LDS.128 (two packed weights per load, warp-broadcast).
// 128 threads/CTA, 256 pixels/CTA -> 16 CTAs per image, 768 total.
// ---------------------------------------------------------------------------
__global__ __launch_bounds__(128) void reduce_kernel(
    const float* __restrict__ vit, const float* __restrict__ wr,
    const float* __restrict__ br)
{
    extern __shared__ unsigned long long ws[];  // [CIN][COUT] packed {w,w}
    const int img = blockIdx.y;

    for (int i = threadIdx.x; i < CIN * COUT; i += 128) {
        const int c = i >> 5, o = i & 31;
        const float v = wr[o * CIN + c];
        unsigned long long p;
        asm("mov.b64 %0, {%1, %2};" : "=l"(p) : "f"(v), "f"(v));
        ws[i] = p;
    }
    __syncthreads();

    const int pix0 = (blockIdx.x * 128 + threadIdx.x) * 2;
    const float* in = vit + (size_t)img * CIN * HW + pix0;

    unsigned long long acc[COUT];
#pragma unroll
    for (int o = 0; o < COUT; o++) acc[o] = 0ull;

#pragma unroll 2
    for (int c = 0; c < CIN; c++) {
        const float2 x = *reinterpret_cast<const float2*>(in + (size_t)c * HW);
        unsigned long long xp;
        asm("mov.b64 %0, {%1, %2};" : "=l"(xp) : "f"(x.x), "f"(x.y));
        const ulonglong2* wrow =
            reinterpret_cast<const ulonglong2*>(ws + c * COUT);
#pragma unroll
        for (int o2 = 0; o2 < 16; o2++) {
            const ulonglong2 wv = wrow[o2];  // LDS.128: 2 packed weights
            asm("fma.rn.f32x2 %0, %1, %2, %0;" : "+l"(acc[2*o2])   : "l"(wv.x), "l"(xp));
            asm("fma.rn.f32x2 %0, %1, %2, %0;" : "+l"(acc[2*o2+1]) : "l"(wv.y), "l"(xp));
        }
    }

    // Epilogue: unpack pixel pairs, add bias, store channel-minor.
    float v0[COUT], v1[COUT];
#pragma unroll
    for (int o = 0; o < COUT; o++) {
        float lo, hi;
        asm("mov.b64 {%0, %1}, %2;" : "=f"(lo), "=f"(hi) : "l"(acc[o]));
        const float b = __ldg(br + o);
        v0[o] = lo + b;
        v1[o] = hi + b;
    }
    float4* out0 = reinterpret_cast<float4*>(
        g_red + ((size_t)img * HW + pix0) * COUT);
#pragma unroll
    for (int j = 0; j < 8; j++)
        out0[j] = make_float4(v0[4*j], v0[4*j+1], v0[4*j+2], v0[4*j+3]);
    float4* out1 = out0 + 8;
#pragma unroll
    for (int j = 0; j < 8; j++)
        out1[j] = make_float4(v1[4*j], v1[4*j+1], v1[4*j+2], v1[4*j+3]);
}

// ---------------------------------------------------------------------------
// Kernel B: backproject 12 views per voxel, average over valid views.
// One thread per voxel (consecutive threads = consecutive z -> coalesced
// output stores per channel, spatially-local gathers served by L2/L1).
// ---------------------------------------------------------------------------
__global__ __launch_bounds__(256) void backproj_kernel(
    const float* __restrict__ proj, float* __restrict__ out)
{
    __shared__ float P[NVW][12];
    const int b = blockIdx.y;
    if (threadIdx.x < NVW * 12) {
        const int v = threadIdx.x / 12, k = threadIdx.x % 12;
        float val = proj[((size_t)b * NVW + v) * 12 + k];
        if (k < 8) val *= 0.25f;  // rows 0,1 divided by STRIDE=4
        P[v][k] = val;
    }
    __syncthreads();

    const int n  = blockIdx.x * 256 + threadIdx.x;
    const int xi = n >> 12, yi = (n >> 6) & 63, zi = n & 63;
    const float wx = xi * 0.04f - 1.28f;
    const float wy = yi * 0.04f - 1.28f;
    const float wz = zi * 0.04f - 1.28f;

    unsigned long long acc[16];
#pragma unroll
    for (int j = 0; j < 16; j++) acc[j] = 0ull;
    float cnt = 0.f;

    for (int v = 0; v < NVW; v++) {
        const float c0 = P[v][0]*wx + P[v][1]*wy + P[v][2]*wz  + P[v][3];
        const float c1 = P[v][4]*wx + P[v][5]*wy + P[v][6]*wz  + P[v][7];
        const float c2 = P[v][8]*wx + P[v][9]*wy + P[v][10]*wz + P[v][11];
        if (c2 > 0.f) {
            const int px = __float2int_rn(c0 / c2);  // round-half-even, IEEE div
            const int py = __float2int_rn(c1 / c2);
            if (((unsigned)px < 64u) && ((unsigned)py < 64u)) {
                cnt += 1.f;
                const float4* f = reinterpret_cast<const float4*>(
                    g_red + (((size_t)(b * NVW + v) * HW) + (py << 6) + px) * COUT);
#pragma unroll
                for (int j = 0; j < 8; j++) {
                    const float4 t = f[j];  // LDG.128, contiguous channels
                    unsigned long long p0, p1;
                    asm("mov.b64 %0, {%1, %2};" : "=l"(p0) : "f"(t.x), "f"(t.y));
                    asm("mov.b64 %0, {%1, %2};" : "=l"(p1) : "f"(t.z), "f"(t.w));
                    asm("add.rn.f32x2 %0, %0, %1;" : "+l"(acc[2*j])   : "l"(p0));
                    asm("add.rn.f32x2 %0, %0, %1;" : "+l"(acc[2*j+1]) : "l"(p1));
                }
            }
        }
    }

    const float inv = (cnt > 0.f) ? (1.f / cnt) : 0.f;
    float* op = out + (size_t)b * COUT * NVOX + n;
#pragma unroll
    for (int j = 0; j < 16; j++) {
        float lo, hi;
        asm("mov.b64 {%0, %1}, %2;" : "=f"(lo), "=f"(hi) : "l"(acc[j]));
        op[(size_t)(2*j)     * NVOX] = lo * inv;
        op[(size_t)(2*j + 1) * NVOX] = hi * inv;
    }
}

// ---------------------------------------------------------------------------
extern "C" void kernel_launch(void* const* d_in, const int* in_sizes, int n_in,
                              void* d_out, int out_size)
{
    const float* vit = (const float*)d_in[0];  // (4,12,384,64,64)
    const float* wr  = (const float*)d_in[1];  // (32,384)
    const float* br  = (const float*)d_in[2];  // (32,)
    const float* pj  = (const float*)d_in[3];  // (4,12,3,4)
    float* out = (float*)d_out;                // (4,32,64,64,64)

    const int smemA = CIN * COUT * 8;  // 96 KB packed weights
    cudaFuncSetAttribute(reduce_kernel,
                         cudaFuncAttributeMaxDynamicSharedMemorySize, smemA);

    dim3 gA(16, NIMG);             // 16 blocks * 128 thr * 2 pix = 4096 pixels
    reduce_kernel<<<gA, 128, smemA>>>(vit, wr, br);

    dim3 gB(NVOX / 256, BS);
    backproj_kernel<<<gB, 256>>>(pj, out);
}

// round 9
// speedup vs baseline: 1.7362x; 1.7362x over previous
#include <cuda_runtime.h>
#include <cstdint>

#define BS   4
#define NVW  12
#define CIN  384
#define COUT 32
#define HW   4096
#define NIMG (BS * NVW)
#define NVOX (64 * 64 * 64)

// Scratch: reduced features in (img, pixel, channel) layout -> 25.2 MB.
__device__ float g_red[(size_t)NIMG * HW * COUT];

// ---------------------------------------------------------------------------
// Kernel A: channel reduce 384 -> 32, packed f32x2 FMAs.
// 256 thr/CTA (16 warps/SM at 2 CTA/SM) + 8-deep explicit load batching
// (MLP=8) to fix the 690 GB/s DRAM ceiling seen in round 5.
// ---------------------------------------------------------------------------
__global__ __launch_bounds__(256, 2) void reduce_kernel(
    const float* __restrict__ vit, const float* __restrict__ wr,
    const float* __restrict__ br)
{
    extern __shared__ unsigned long long ws[];  // [CIN][COUT] packed {w,w}
    const int img = blockIdx.y;

    for (int i = threadIdx.x; i < CIN * COUT; i += 256) {
        const int c = i >> 5, o = i & 31;
        const float v = wr[o * CIN + c];
        unsigned long long p;
        asm("mov.b64 %0, {%1, %2};" : "=l"(p) : "f"(v), "f"(v));
        ws[i] = p;
    }
    __syncthreads();

    const int pix0 = (blockIdx.x * 256 + threadIdx.x) * 2;
    const float* in = vit + (size_t)img * CIN * HW + pix0;

    unsigned long long acc[COUT];
#pragma unroll
    for (int o = 0; o < COUT; o++) acc[o] = 0ull;

    for (int c0 = 0; c0 < CIN; c0 += 8) {
        float2 xr[8];
#pragma unroll
        for (int u = 0; u < 8; u++)   // 8 loads in flight before any use
            xr[u] = *reinterpret_cast<const float2*>(in + (size_t)(c0 + u) * HW);
#pragma unroll
        for (int u = 0; u < 8; u++) {
            unsigned long long xp;
            asm("mov.b64 %0, {%1, %2};" : "=l"(xp) : "f"(xr[u].x), "f"(xr[u].y));
            const ulonglong2* wrow =
                reinterpret_cast<const ulonglong2*>(ws + (c0 + u) * COUT);
#pragma unroll
            for (int o2 = 0; o2 < 16; o2++) {
                const ulonglong2 wv = wrow[o2];  // LDS.128, warp-broadcast
                asm("fma.rn.f32x2 %0, %1, %2, %0;" : "+l"(acc[2*o2])   : "l"(wv.x), "l"(xp));
                asm("fma.rn.f32x2 %0, %1, %2, %0;" : "+l"(acc[2*o2+1]) : "l"(wv.y), "l"(xp));
            }
        }
    }

    float v0[COUT], v1[COUT];
#pragma unroll
    for (int o = 0; o < COUT; o++) {
        float lo, hi;
        asm("mov.b64 {%0, %1}, %2;" : "=f"(lo), "=f"(hi) : "l"(acc[o]));
        const float b = __ldg(br + o);
        v0[o] = lo + b;
        v1[o] = hi + b;
    }
    float4* out0 = reinterpret_cast<float4*>(
        g_red + ((size_t)img * HW + pix0) * COUT);
#pragma unroll
    for (int j = 0; j < 8; j++)
        out0[j] = make_float4(v0[4*j], v0[4*j+1], v0[4*j+2], v0[4*j+3]);
    float4* out1 = out0 + 8;
#pragma unroll
    for (int j = 0; j < 8; j++)
        out1[j] = make_float4(v1[4*j], v1[4*j+1], v1[4*j+2], v1[4*j+3]);
}

// ---------------------------------------------------------------------------
// Kernel B: backproject. Restructured vs round 5 (L1tex-wavefront-bound):
//   Phase 1: per-CTA smem table of projected pixel ids (u16, 0xFFFF=invalid),
//            one projection per voxel-view (no 8x redundant div).
//   Phase 2: lane = 8 channel-groups x 4 z-slots; thread owns 4 consecutive
//            z voxels x 4 channels. Lanes 0-7 of a z-slot read ONE contiguous
//            128B feature line; the float4 is reused across consecutive z
//            that hit the same pixel (~75% of steps).
// CTA = 256 thr = 8 warps = 2 (x,y) columns of 64 z.
// ---------------------------------------------------------------------------
__global__ __launch_bounds__(256) void backproj_kernel(
    const float* __restrict__ proj, float* __restrict__ out)
{
    __shared__ float P[NVW][12];
    __shared__ unsigned short pixt[2 * NVW * 64];  // [col][view][z]

    const int b   = blockIdx.y;
    const int tid = threadIdx.x;

    if (tid < NVW * 12) {
        const int v = tid / 12, k = tid % 12;
        float val = proj[((size_t)b * NVW + v) * 12 + k];
        if (k < 8) val *= 0.25f;  // rows 0,1 divided by STRIDE=4
        P[v][k] = val;
    }
    __syncthreads();

    // ---- Phase 1: pixel table (1536 entries, 6 per thread) ----
#pragma unroll
    for (int k = 0; k < 6; k++) {
        const int e   = tid + k * 256;
        const int zi  = e & 63;
        const int t2  = e >> 6;
        const int v   = t2 % NVW;
        const int col = t2 / NVW;               // 0 or 1
        const int cg  = blockIdx.x * 2 + col;   // global column
        const float wx = (cg >> 6) * 0.04f - 1.28f;
        const float wy = (cg & 63) * 0.04f - 1.28f;
        const float wz = zi * 0.04f - 1.28f;

        const float c0 = P[v][0]*wx + P[v][1]*wy + P[v][2]*wz  + P[v][3];
        const float c1 = P[v][4]*wx + P[v][5]*wy + P[v][6]*wz  + P[v][7];
        const float c2 = P[v][8]*wx + P[v][9]*wy + P[v][10]*wz + P[v][11];

        unsigned short pv = 0xFFFFu;
        if (c2 > 0.f) {
            const int px = __float2int_rn(c0 / c2);  // round-half-even, IEEE div
            const int py = __float2int_rn(c1 / c2);
            if (((unsigned)px < 64u) && ((unsigned)py < 64u))
                pv = (unsigned short)((py << 6) + px);
        }
        pixt[e] = pv;
    }
    __syncthreads();

    // ---- Phase 2: gather + accumulate ----
    const int warp = tid >> 5, lane = tid & 31;
    const int col  = warp >> 2;                     // 0..1
    const int zb   = ((warp & 3) << 4) + ((lane >> 3) << 2);  // z base, mult of 4
    const int chg  = lane & 7;                      // channel group (4 floats)
    const int colg = blockIdx.x * 2 + col;          // global column

    float4 acc[4];
#pragma unroll
    for (int z = 0; z < 4; z++) acc[z] = make_float4(0.f, 0.f, 0.f, 0.f);
    float cnt[4] = {0.f, 0.f, 0.f, 0.f};

    for (int v = 0; v < NVW; v++) {
        // 4 pixel ids for my 4 z's: one LDS.64
        const unsigned short* pp = &pixt[(col * NVW + v) * 64 + zb];
        ushort4 p4 = *reinterpret_cast<const ushort4*>(pp);
        const unsigned short p[4] = {p4.x, p4.y, p4.z, p4.w};

        const float4* fbase = reinterpret_cast<const float4*>(
            g_red + ((size_t)(b * NVW + v) * HW) * COUT) + chg;
        int curp = -1;
        float4 cur = make_float4(0.f, 0.f, 0.f, 0.f);
#pragma unroll
        for (int z = 0; z < 4; z++) {
            if (p[z] != 0xFFFFu) {
                if ((int)p[z] != curp) {            // reuse across same-pixel z's
                    cur  = fbase[(size_t)p[z] * 8]; // LDG.128, lanes 0-7 = 1 line
                    curp = (int)p[z];
                }
                acc[z].x += cur.x; acc[z].y += cur.y;
                acc[z].z += cur.z; acc[z].w += cur.w;
                cnt[z] += 1.f;
            }
        }
    }

    // ---- Epilogue: normalize, transpose (z,chan) -> per-channel float4 of 4 z ----
    float inv[4];
#pragma unroll
    for (int z = 0; z < 4; z++) inv[z] = (cnt[z] > 0.f) ? (1.f / cnt[z]) : 0.f;

    const int n0 = colg * 64 + zb;  // 4 consecutive voxel ids, 16B aligned
    float* ob = out + (size_t)b * COUT * NVOX + (size_t)(chg * 4) * NVOX + n0;
#pragma unroll
    for (int c = 0; c < 4; c++) {
        float4 s;
        s.x = ((&acc[0].x)[c]) * inv[0];
        s.y = ((&acc[1].x)[c]) * inv[1];
        s.z = ((&acc[2].x)[c]) * inv[2];
        s.w = ((&acc[3].x)[c]) * inv[3];
        *reinterpret_cast<float4*>(ob + (size_t)c * NVOX) = s;
    }
}

// ---------------------------------------------------------------------------
extern "C" void kernel_launch(void* const* d_in, const int* in_sizes, int n_in,
                              void* d_out, int out_size)
{
    const float* vit = (const float*)d_in[0];  // (4,12,384,64,64)
    const float* wr  = (const float*)d_in[1];  // (32,384)
    const float* br  = (const float*)d_in[2];  // (32,)
    const float* pj  = (const float*)d_in[3];  // (4,12,3,4)
    float* out = (float*)d_out;                // (4,32,64,64,64)

    const int smemA = CIN * COUT * 8;  // 96 KB packed weights
    cudaFuncSetAttribute(reduce_kernel,
                         cudaFuncAttributeMaxDynamicSharedMemorySize, smemA);

    dim3 gA(8, NIMG);              // 8 blocks * 256 thr * 2 pix = 4096 pixels
    reduce_kernel<<<gA, 256, smemA>>>(vit, wr, br);

    dim3 gB(2048, BS);             // 2048 CTAs * 2 columns * 64 z = 262144 voxels
    backproj_kernel<<<gB, 256>>>(pj, out);
}

// round 11
// speedup vs baseline: 2.1237x; 1.2231x over previous
#include <cuda_runtime.h>
#include <cstdint>

#define BS   4
#define NVW  12
#define CIN  384
#define COUT 32
#define HW   4096
#define NIMG (BS * NVW)
#define NVOX (64 * 64 * 64)

// Scratch: reduced features in (img, pixel, channel) layout -> 25.2 MB.
__device__ float g_red[(size_t)NIMG * HW * COUT];

// ---------------------------------------------------------------------------
// Kernel A: channel reduce 384 -> 32.
// v2: pack OUTPUT-CHANNEL pairs (not pixel pairs). Weights un-duplicated in
// smem (48 KB, ws[c][o]); one LDS.128 = 4 distinct weights = 2 FFMA2 operands
// -> LDS count halved vs R9 (8/channel instead of 16). Input splatted {x,x}.
// 2 pixels/thread, MLP=8 load batching kept.
// ---------------------------------------------------------------------------
__global__ __launch_bounds__(256, 2) void reduce_kernel(
    const float* __restrict__ vit, const float* __restrict__ wr,
    const float* __restrict__ br)
{
    extern __shared__ float ws[];  // [CIN][COUT] floats, 48 KB
    const int img = blockIdx.y;

    for (int i = threadIdx.x; i < CIN * COUT; i += 256) {
        const int c = i >> 5, o = i & 31;
        ws[i] = wr[o * CIN + c];
    }
    __syncthreads();

    const int pix0 = (blockIdx.x * 256 + threadIdx.x) * 2;
    const float* in = vit + (size_t)img * CIN * HW + pix0;

    // acc0[j] = pixel0 channels {2j,2j+1}; acc1[j] = pixel1 channels {2j,2j+1}
    unsigned long long acc0[16], acc1[16];
#pragma unroll
    for (int j = 0; j < 16; j++) { acc0[j] = 0ull; acc1[j] = 0ull; }

    for (int c0 = 0; c0 < CIN; c0 += 8) {
        float2 xr[8];
#pragma unroll
        for (int u = 0; u < 8; u++)   // 8 loads in flight before any use
            xr[u] = *reinterpret_cast<const float2*>(in + (size_t)(c0 + u) * HW);
#pragma unroll
        for (int u = 0; u < 8; u++) {
            unsigned long long xa, xb;
            asm("mov.b64 %0, {%1, %1};" : "=l"(xa) : "f"(xr[u].x));
            asm("mov.b64 %0, {%1, %1};" : "=l"(xb) : "f"(xr[u].y));
            const ulonglong2* wrow =
                reinterpret_cast<const ulonglong2*>(ws + (c0 + u) * COUT);
#pragma unroll
            for (int o4 = 0; o4 < 8; o4++) {
                const ulonglong2 wv = wrow[o4];  // LDS.128: 4 distinct weights
                asm("fma.rn.f32x2 %0, %1, %2, %0;" : "+l"(acc0[2*o4])   : "l"(wv.x), "l"(xa));
                asm("fma.rn.f32x2 %0, %1, %2, %0;" : "+l"(acc0[2*o4+1]) : "l"(wv.y), "l"(xa));
                asm("fma.rn.f32x2 %0, %1, %2, %0;" : "+l"(acc1[2*o4])   : "l"(wv.x), "l"(xb));
                asm("fma.rn.f32x2 %0, %1, %2, %0;" : "+l"(acc1[2*o4+1]) : "l"(wv.y), "l"(xb));
            }
        }
    }

    // Epilogue: unpack (already channel-pair ordered), add bias, store.
    float v0[COUT], v1[COUT];
#pragma unroll
    for (int j = 0; j < 16; j++) {
        float a, bq, c, d;
        asm("mov.b64 {%0, %1}, %2;" : "=f"(a), "=f"(bq) : "l"(acc0[j]));
        asm("mov.b64 {%0, %1}, %2;" : "=f"(c), "=f"(d)  : "l"(acc1[j]));
        const float b0 = __ldg(br + 2*j), b1 = __ldg(br + 2*j + 1);
        v0[2*j] = a + b0; v0[2*j+1] = bq + b1;
        v1[2*j] = c + b0; v1[2*j+1] = d + b1;
    }
    float4* out0 = reinterpret_cast<float4*>(
        g_red + ((size_t)img * HW + pix0) * COUT);
#pragma unroll
    for (int k = 0; k < 8; k++)
        out0[k] = make_float4(v0[4*k], v0[4*k+1], v0[4*k+2], v0[4*k+3]);
    float4* out1 = out0 + 8;
#pragma unroll
    for (int k = 0; k < 8; k++)
        out1[k] = make_float4(v1[4*k], v1[4*k+1], v1[4*k+2], v1[4*k+3]);
}

// ---------------------------------------------------------------------------
// Kernel B: backproject. v2 vs R9 (issue-bound, alu 29.3%):
//   - pixel table holds pre-shifted u32 BYTE offsets (pix*128); kills the
//     ushort4 unpack (~5 alu/view) and one IMAD per load.
//   - packed f32x2 accumulation: fma-pipe ops per z-view 12 -> 7.
//   - same-pixel dedup kept (protects L1, which R6 fixed).
// ---------------------------------------------------------------------------
__global__ __launch_bounds__(256) void backproj_kernel(
    const float* __restrict__ proj, float* __restrict__ out)
{
    __shared__ float P[NVW][12];
    __shared__ unsigned int pixt[2 * NVW * 64];  // [col][view][z] byte offsets

    const int b   = blockIdx.y;
    const int tid = threadIdx.x;

    if (tid < NVW * 12) {
        const int v = tid / 12, k = tid % 12;
        float val = proj[((size_t)b * NVW + v) * 12 + k];
        if (k < 8) val *= 0.25f;  // rows 0,1 divided by STRIDE=4
        P[v][k] = val;
    }
    __syncthreads();

    // ---- Phase 1: pixel table (1536 entries, 6 per thread) ----
#pragma unroll
    for (int k = 0; k < 6; k++) {
        const int e   = tid + k * 256;
        const int zi  = e & 63;
        const int t2  = e >> 6;
        const int v   = t2 % NVW;
        const int col = t2 / NVW;               // 0 or 1
        const int cg  = blockIdx.x * 2 + col;   // global column
        const float wx = (cg >> 6) * 0.04f - 1.28f;
        const float wy = (cg & 63) * 0.04f - 1.28f;
        const float wz = zi * 0.04f - 1.28f;

        const float c0 = P[v][0]*wx + P[v][1]*wy + P[v][2]*wz  + P[v][3];
        const float c1 = P[v][4]*wx + P[v][5]*wy + P[v][6]*wz  + P[v][7];
        const float c2 = P[v][8]*wx + P[v][9]*wy + P[v][10]*wz + P[v][11];

        unsigned int pv = 0xFFFFFFFFu;
        if (c2 > 0.f) {
            const int px = __float2int_rn(c0 / c2);  // round-half-even, IEEE div
            const int py = __float2int_rn(c1 / c2);
            if (((unsigned)px < 64u) && ((unsigned)py < 64u))
                pv = (unsigned int)(((py << 6) + px) << 7);  // *128 bytes
        }
        pixt[e] = pv;
    }
    __syncthreads();

    // ---- Phase 2: gather + accumulate ----
    const int warp = tid >> 5, lane = tid & 31;
    const int col  = warp >> 2;                     // 0..1
    const int zb   = ((warp & 3) << 4) + ((lane >> 3) << 2);  // z base, mult of 4
    const int chg  = lane & 7;                      // channel group (4 floats)
    const int colg = blockIdx.x * 2 + col;          // global column

    unsigned long long acc2[8];                     // [z][2]: {c0,c1},{c2,c3}
#pragma unroll
    for (int j = 0; j < 8; j++) acc2[j] = 0ull;
    float cnt[4] = {0.f, 0.f, 0.f, 0.f};

    for (int v = 0; v < NVW; v++) {
        const uint4 o4 = *reinterpret_cast<const uint4*>(
            &pixt[(col * NVW + v) * 64 + zb]);      // LDS.128
        const unsigned int off[4] = {o4.x, o4.y, o4.z, o4.w};

        const char* fb = reinterpret_cast<const char*>(
            g_red + ((size_t)(b * NVW + v) * HW) * COUT) + chg * 16;
        unsigned int curo = 0xFFFFFFFFu;
        unsigned long long cu0 = 0ull, cu1 = 0ull;
#pragma unroll
        for (int z = 0; z < 4; z++) {
            if (off[z] != 0xFFFFFFFFu) {
                if (off[z] != curo) {               // reuse across same-pixel z's
                    const float4 t = *reinterpret_cast<const float4*>(fb + off[z]);
                    asm("mov.b64 %0, {%1, %2};" : "=l"(cu0) : "f"(t.x), "f"(t.y));
                    asm("mov.b64 %0, {%1, %2};" : "=l"(cu1) : "f"(t.z), "f"(t.w));
                    curo = off[z];
                }
                asm("add.rn.f32x2 %0, %0, %1;" : "+l"(acc2[2*z])   : "l"(cu0));
                asm("add.rn.f32x2 %0, %0, %1;" : "+l"(acc2[2*z+1]) : "l"(cu1));
                cnt[z] += 1.f;
            }
        }
    }

    // ---- Epilogue: normalize, transpose (z,chan) -> per-channel float4 of 4 z ----
    float s[4][4];
#pragma unroll
    for (int z = 0; z < 4; z++) {
        const float inv = (cnt[z] > 0.f) ? (1.f / cnt[z]) : 0.f;
        float a, bq, c, d;
        asm("mov.b64 {%0, %1}, %2;" : "=f"(a), "=f"(bq) : "l"(acc2[2*z]));
        asm("mov.b64 {%0, %1}, %2;" : "=f"(c), "=f"(d)  : "l"(acc2[2*z+1]));
        s[z][0] = a * inv; s[z][1] = bq * inv; s[z][2] = c * inv; s[z][3] = d * inv;
    }

    const int n0 = colg * 64 + zb;  // 4 consecutive voxel ids, 16B aligned
    float* ob = out + (size_t)b * COUT * NVOX + (size_t)(chg * 4) * NVOX + n0;
#pragma unroll
    for (int c = 0; c < 4; c++) {
        float4 w4;
        w4.x = s[0][c]; w4.y = s[1][c]; w4.z = s[2][c]; w4.w = s[3][c];
        *reinterpret_cast<float4*>(ob + (size_t)c * NVOX) = w4;
    }
}

// ---------------------------------------------------------------------------
extern "C" void kernel_launch(void* const* d_in, const int* in_sizes, int n_in,
                              void* d_out, int out_size)
{
    const float* vit = (const float*)d_in[0];  // (4,12,384,64,64)
    const float* wr  = (const float*)d_in[1];  // (32,384)
    const float* br  = (const float*)d_in[2];  // (32,)
    const float* pj  = (const float*)d_in[3];  // (4,12,3,4)
    float* out = (float*)d_out;                // (4,32,64,64,64)

    const int smemA = CIN * COUT * 4;  // 48 KB un-duplicated weights
    cudaFuncSetAttribute(reduce_kernel,
                         cudaFuncAttributeMaxDynamicSharedMemorySize, smemA);

    dim3 gA(8, NIMG);              // 8 blocks * 256 thr * 2 pix = 4096 pixels
    reduce_kernel<<<gA, 256, smemA>>>(vit, wr, br);

    dim3 gB(2048, BS);             // 2048 CTAs * 2 columns * 64 z = 262144 voxels
    backproj_kernel<<<gB, 256>>>(pj, out);
}